// round 7
// baseline (speedup 1.0000x reference)
#include <cuda_runtime.h>
#include <cuda_bf16.h>
#include <cstdint>

#define MROWS   131072
#define NDIM    16
#define NBINS   8
#define NELEM   (MROWS * NDIM)          // 2,097,152
#define MIN_BW  0.001f
#define MIN_KS  0.001f

__device__ __forceinline__ float softplus_f(float v) {
    return (v > 15.0f) ? v : __logf(1.0f + __expf(v));
}

__device__ __forceinline__ float4 ldcs4(const float* p) {
    return __ldcs(reinterpret_cast<const float4*>(p));
}

__device__ __forceinline__ uint32_t smem_u32(const void* p) {
    uint32_t a;
    asm("{ .reg .u64 t; cvta.to.shared.u64 t, %1; cvt.u32.u64 %0, t; }"
        : "=r"(a) : "l"(p));
    return a;
}

__device__ __forceinline__ void cpasync16(uint32_t dst, const float* src) {
    asm volatile("cp.async.cg.shared.global [%0], [%1], 16;"
                 :: "r"(dst), "l"(src) : "memory");
}

// Search + spline for one transform, bins (bw/bh) already normalized.
__device__ __forceinline__ float spline_eval(float x, float shift,
                                             const float* bw, const float* bh,
                                             const float* srow,
                                             float& ladsum)
{
    // forward periodic shift: arg = x + shift + 1 in [0,3); mod 2, -1
    float arg = x + shift + 1.0f;
    arg = (arg >= 2.0f) ? arg - 2.0f : arg;
    float xs = arg - 1.0f;

    // fused bin search + gather — select form (FSEL, pred-as-data)
    float cum = -1.0f + bw[0];
    float x0  = -1.0f;
    float y0  = -1.0f;
    float wk  = bw[0], hk = bh[0];
    int   idx = 0;
    #pragma unroll
    for (int j = 0; j < 7; ++j) {
        bool g = (xs >= cum);
        idx = g ? (j + 1)     : idx;
        x0  = g ? cum         : x0;
        y0  = g ? (y0 + bh[j]): y0;
        wk  = g ? bw[j + 1]   : wk;
        hk  = g ? bh[j + 1]   : hk;
        if (j < 6) cum += bw[j + 1];
    }

    // flanking knot slopes from smem (clamped address, selected value)
    int a0 = (idx > 0) ? idx - 1 : 0;
    int a1 = (idx < 7) ? idx : 6;
    float v0 = srow[a0];
    float v1 = srow[a1];
    float d0 = (idx > 0) ? softplus_f(v0) + MIN_KS : 1.0f;
    float d1 = (idx < 7) ? softplus_f(v1) + MIN_KS : 1.0f;

    float rwk  = __fdividef(1.0f, wk);
    float sk   = hk * rwk;
    float t    = (xs - x0) * rwk;
    float omt  = 1.0f - t;
    float tomt = t * omt;
    float denom = sk + (d1 + d0 - 2.0f * sk) * tomt;
    float rden  = __fdividef(1.0f, denom);
    float y = y0 + hk * (sk * t * t + d0 * tomt) * rden;

    float numer = d1 * t * t + 2.0f * sk * tomt + d0 * omt * omt;
    ladsum += __logf(sk * sk * numer * rden * rden);

    // inverse periodic shift: arg2 = y - shift + 3 in [1, 4]
    float arg2 = y - shift + 3.0f;
    arg2 = (arg2 >= 2.0f) ? arg2 - 2.0f : arg2;
    arg2 = (arg2 >= 2.0f) ? arg2 - 2.0f : arg2;
    return arg2 - 1.0f;
}

__device__ __forceinline__ void exp8(const float4& a, const float4& b, float* e) {
    e[0] = __expf(a.x); e[1] = __expf(a.y); e[2] = __expf(a.z); e[3] = __expf(a.w);
    e[4] = __expf(b.x); e[5] = __expf(b.y); e[6] = __expf(b.z); e[7] = __expf(b.w);
}

__device__ __forceinline__ float sum8(const float* e) {
    return ((e[0] + e[1]) + (e[2] + e[3])) + ((e[4] + e[5]) + (e[6] + e[7]));
}

__global__ __launch_bounds__(256, 5)
void rqs_coupling_kernel(const float* __restrict__ x_in,
                         const float* __restrict__ w,
                         const float* __restrict__ h,
                         const float* __restrict__ s,
                         const float* __restrict__ shifts,
                         float* __restrict__ out)
{
    // s slope staging: [transform][warp][224 floats] — warp-private regions
    __shared__ __align__(16) float s_stage[2][8][224];

    const float cdom = 2.0f - (float)NBINS * MIN_BW;   // 1.992

    int e    = blockIdx.x * 256 + threadIdx.x;
    int lane = threadIdx.x & 31;
    int warp = threadIdx.x >> 5;

    size_t b0_128 = (size_t)e * 8u;
    size_t b1_128 = ((size_t)NELEM + (size_t)e) * 8u;

    size_t sbase0 = (size_t)(blockIdx.x * 256 + warp * 32) * 7u;
    size_t sbase1 = sbase0 + (size_t)NELEM * 7u;

    // ---- s staging via cp.async: no register landing, issued first ----
    uint32_t st0 = smem_u32(&s_stage[0][warp][4 * lane]);
    uint32_t st1 = smem_u32(&s_stage[1][warp][4 * lane]);
    cpasync16(st0, s + sbase0 + 4 * lane);
    cpasync16(st1, s + sbase1 + 4 * lane);
    if (lane < 24) {
        cpasync16(st0 + 512, s + sbase0 + 128 + 4 * lane);
        cpasync16(st1 + 512, s + sbase1 + 128 + 4 * lane);
    }
    asm volatile("cp.async.commit_group;" ::: "memory");

    // ---- front-batched register loads ----
    float  x   = __ldcs(x_in + e);
    float  sh0 = __ldcs(shifts + e);
    float  sh1 = __ldcs(shifts + NELEM + e);
    float4 w0a = ldcs4(w + b0_128);     float4 w0b = ldcs4(w + b0_128 + 4);
    float4 h0a = ldcs4(h + b0_128);     float4 h0b = ldcs4(h + b0_128 + 4);
    float4 w1a = ldcs4(w + b1_128);     float4 w1b = ldcs4(w + b1_128 + 4);
    float4 h1a = ldcs4(h + b1_128);     float4 h1b = ldcs4(h + b1_128 + 4);

    // ---- interleaved softmax prep for BOTH transforms (ILP-2) ----
    float ew0[8], eh0[8], ew1[8], eh1[8];
    exp8(w0a, w0b, ew0);
    exp8(w1a, w1b, ew1);
    exp8(h0a, h0b, eh0);
    exp8(h1a, h1b, eh1);

    float cw0 = __fdividef(cdom, sum8(ew0));
    float cw1 = __fdividef(cdom, sum8(ew1));
    float ch0 = __fdividef(cdom, sum8(eh0));
    float ch1 = __fdividef(cdom, sum8(eh1));

    float bw0[8], bh0[8];
    #pragma unroll
    for (int j = 0; j < 8; ++j) {
        bw0[j] = ew0[j] * cw0 + MIN_BW;
        bh0[j] = eh0[j] * ch0 + MIN_BW;
    }

    // s slopes must be resident before spline evals
    asm volatile("cp.async.wait_group 0;" ::: "memory");
    __syncwarp();

    const float* srow0 = &s_stage[0][warp][7 * lane];
    const float* srow1 = &s_stage[1][warp][7 * lane];

    float ladsum = 0.0f;
    x = spline_eval(x, sh0, bw0, bh0, srow0, ladsum);

    float bw1[8], bh1[8];
    #pragma unroll
    for (int j = 0; j < 8; ++j) {
        bw1[j] = ew1[j] * cw1 + MIN_BW;
        bh1[j] = eh1[j] * ch1 + MIN_BW;
    }

    x = spline_eval(x, sh1, bw1, bh1, srow1, ladsum);

    __stcs(out + e, x);
    __stcs(out + NELEM + e, ladsum);
}

extern "C" void kernel_launch(void* const* d_in, const int* in_sizes, int n_in,
                              void* d_out, int out_size) {
    const float* x      = (const float*)d_in[0];
    const float* w      = (const float*)d_in[1];
    const float* h      = (const float*)d_in[2];
    const float* s      = (const float*)d_in[3];
    const float* shifts = (const float*)d_in[4];
    float* out = (float*)d_out;

    rqs_coupling_kernel<<<NELEM / 256, 256>>>(x, w, h, s, shifts, out);
}